// round 8
// baseline (speedup 1.0000x reference)
#include <cuda_runtime.h>

// ---------------- problem constants (max sizes for static scratch) ----------
#define NN   50000
#define EE   800000

// ---------------- device scratch (no allocations allowed) -------------------
static __device__ float g_agg[(size_t)NN * 512];    // per-relation mean of neighbor feats
static __device__ float g_bufA[(size_t)NN * 128];   // layer activations (ping)
static __device__ float g_bufB[(size_t)NN * 128];   // layer activations (pong)
static __device__ float g_q[16 * 64];               // relu(question @ qn_W + qn_b)
static __device__ int   g_cnt4[NN * 4];             // per-(node,relation) in-degree
static __device__ float g_icnt[NN * 4];             // 1/max(cnt,1)
static __device__ int   g_deg[NN];                  // total in-degree
static __device__ int   g_offs[NN + 1];             // CSR row offsets (by dst)
static __device__ int   g_cursor[NN];               // fill cursors
static __device__ int   g_csr[EE];                  // packed (src<<2)|etype, grouped by dst

// ---------------- small kernels ---------------------------------------------

// q = relu(question_embedding @ qn_W + qn_b)   [16 x 64], K = 768
__global__ void q_kernel(const float* __restrict__ qe,
                         const float* __restrict__ W,
                         const float* __restrict__ b) {
    int g = blockIdx.x;
    int j = threadIdx.x;
    const float* qr = qe + (size_t)g * 768;
    float s = b[j];
    #pragma unroll 4
    for (int k = 0; k < 768; k++)
        s = fmaf(qr[k], W[(size_t)k * 64 + j], s);
    g_q[g * 64 + j] = fmaxf(s, 0.f);
}

__global__ void zero_cnt_kernel(int n4) {
    int i = blockIdx.x * 256 + threadIdx.x;
    if (i < n4) g_cnt4[i] = 0;
}

__global__ void count_kernel(const int* __restrict__ dst,
                             const int* __restrict__ et, int E) {
    int e = blockIdx.x * 256 + threadIdx.x;
    if (e < E) atomicAdd(&g_cnt4[dst[e] * 4 + et[e]], 1);
}

__global__ void prep_kernel(int n) {
    int i = blockIdx.x * 256 + threadIdx.x;
    if (i < n) {
        int d = 0;
        #pragma unroll
        for (int r = 0; r < 4; r++) {
            int c = g_cnt4[i * 4 + r];
            d += c;
            g_icnt[i * 4 + r] = 1.f / (float)(c > 0 ? c : 1);
        }
        g_deg[i] = d;
    }
}

// single-block exclusive scan over g_deg -> g_offs (and copies into g_cursor)
__global__ void scan_kernel(int n) {
    __shared__ int s[1024];
    __shared__ int carry_s;
    int t = threadIdx.x;
    if (t == 0) carry_s = 0;
    __syncthreads();
    for (int base = 0; base < n; base += 1024) {
        int v = (base + t < n) ? g_deg[base + t] : 0;
        s[t] = v;
        __syncthreads();
        for (int off = 1; off < 1024; off <<= 1) {
            int x = (t >= off) ? s[t - off] : 0;
            __syncthreads();
            s[t] += x;
            __syncthreads();
        }
        int incl = s[t];
        int ex = carry_s + incl - v;
        if (base + t < n) { g_offs[base + t] = ex; g_cursor[base + t] = ex; }
        __syncthreads();
        if (t == 1023) carry_s += s[1023];
        __syncthreads();
    }
    if (t == 0) g_offs[n] = carry_s;
}

__global__ void fill_kernel(const int* __restrict__ src,
                            const int* __restrict__ dst,
                            const int* __restrict__ et, int E) {
    int e = blockIdx.x * 256 + threadIdx.x;
    if (e < E) {
        int d = dst[e];
        int pos = atomicAdd(&g_cursor[d], 1);
        g_csr[pos] = (src[e] << 2) | et[e];
    }
}

// comb[:, 64:128] = q[batch[i]]
__global__ void qfill_kernel(const int* __restrict__ batch, int n) {
    int t = blockIdx.x * 256 + threadIdx.x;
    if (t < n * 64) {
        int i = t >> 6, j = t & 63;
        g_bufA[(size_t)i * 128 + 64 + j] = g_q[batch[i] * 64 + j];
    }
}

// ---------------- aggregation in INPUT space: warp per node -----------------
// g_agg[w, r*128 + f] = mean over r-neighbors of act[src, f]
// Gather working set = act (25.6 MB) -> fully L2-resident.
__global__ void __launch_bounds__(256) aggx_kernel(const float* __restrict__ act,
                                                   int M) {
    int w = (blockIdx.x * 256 + threadIdx.x) >> 5;
    int lane = threadIdx.x & 31;
    if (w >= M) return;
    float a0[4] = {0,0,0,0}, a1[4] = {0,0,0,0};
    float a2[4] = {0,0,0,0}, a3[4] = {0,0,0,0};
    int beg = g_offs[w], end = g_offs[w + 1];
    for (int e = beg; e < end; e++) {
        int p = g_csr[e];
        float4 v = *(const float4*)(act + (size_t)(p >> 2) * 128 + lane * 4);
        int r = p & 3;   // uniform across the warp (one edge per warp-iteration)
        if (r == 0)      { a0[0]+=v.x; a0[1]+=v.y; a0[2]+=v.z; a0[3]+=v.w; }
        else if (r == 1) { a1[0]+=v.x; a1[1]+=v.y; a1[2]+=v.z; a1[3]+=v.w; }
        else if (r == 2) { a2[0]+=v.x; a2[1]+=v.y; a2[2]+=v.z; a2[3]+=v.w; }
        else             { a3[0]+=v.x; a3[1]+=v.y; a3[2]+=v.z; a3[3]+=v.w; }
    }
    const float* icn = g_icnt + w * 4;
    float s0 = icn[0], s1 = icn[1], s2 = icn[2], s3 = icn[3];
    float* o = g_agg + (size_t)w * 512 + lane * 4;
    *(float4*)(o)       = make_float4(a0[0]*s0, a0[1]*s0, a0[2]*s0, a0[3]*s0);
    *(float4*)(o + 128) = make_float4(a1[0]*s1, a1[1]*s1, a1[2]*s1, a1[3]*s1);
    *(float4*)(o + 256) = make_float4(a2[0]*s2, a2[1]*s2, a2[2]*s2, a2[3]*s2);
    *(float4*)(o + 384) = make_float4(a3[0]*s3, a3[1]*s3, a3[2]*s3, a3[3]*s3);
}

// ---------------- TF32 tensor-core GEMM with fused bias+relu ----------------
// out[M,OUT] = [A0 | A1] @ [root; W]  where A0=[M,128] act, A1=[M,512] agg,
// root=[128,OUT], W=[512,OUT] (= [R,128,OUT] contiguous). K = 640.
// block tile 128x64, 8 warps (4x2), warp tile 32x32, mma m16n8k8 tf32.

__device__ __forceinline__ unsigned f2tf(float f) {
    unsigned u;
    asm("cvt.rna.tf32.f32 %0, %1;" : "=r"(u) : "f"(f));
    return u;
}

__device__ __forceinline__ void mma_tf32(float* c, const unsigned* a, const unsigned* b) {
    asm volatile("mma.sync.aligned.m16n8k8.row.col.f32.tf32.tf32.f32 "
                 "{%0,%1,%2,%3}, {%4,%5,%6,%7}, {%8,%9}, {%0,%1,%2,%3};"
                 : "+f"(c[0]), "+f"(c[1]), "+f"(c[2]), "+f"(c[3])
                 : "r"(a[0]), "r"(a[1]), "r"(a[2]), "r"(a[3]),
                   "r"(b[0]), "r"(b[1]));
}

__global__ void __launch_bounds__(256) gemm_tc_kernel(
        const float* __restrict__ A0, const float* __restrict__ A1,
        const float* __restrict__ Broot, const float* __restrict__ Bw,
        const float* __restrict__ bias,
        float* __restrict__ out, int ldo, int M, int OUT, int relu) {
    __shared__ unsigned As[128][36];   // [m][k], ld 36 -> conflict-free frag loads
    __shared__ unsigned Bs[32][72];    // [k][n], ld 72 -> conflict-free frag loads
    int tid = threadIdx.x;
    int warp = tid >> 5, lane = tid & 31;
    int wm = warp >> 1, wn = warp & 1;
    int lg = lane >> 2;   // groupID
    int lq = lane & 3;    // threadID_in_group
    int row0 = blockIdx.y * 128, col0 = blockIdx.x * 64;

    float acc[2][4][4];
    #pragma unroll
    for (int t = 0; t < 2; t++)
        #pragma unroll
        for (int j = 0; j < 4; j++)
            #pragma unroll
            for (int v = 0; v < 4; v++) acc[t][j][v] = 0.f;

    int ar = tid >> 3;            // 0..31: A row within 32-row pass
    int ak = (tid & 7) * 4;       // k quad within 32-wide chunk
    int bk = tid >> 4;            // 0..15: B k within 16-row pass
    int bn = (tid & 15) * 4;      // n quad

    for (int k0 = 0; k0 < 640; k0 += 32) {
        float4 av[4], bv[2];
        #pragma unroll
        for (int p = 0; p < 4; p++) {
            int r = row0 + p * 32 + ar;
            if (r >= M) { av[p] = make_float4(0.f, 0.f, 0.f, 0.f); continue; }
            av[p] = (k0 < 128)
                  ? *(const float4*)(A0 + (size_t)r * 128 + k0 + ak)
                  : *(const float4*)(A1 + (size_t)r * 512 + (k0 - 128) + ak);
        }
        #pragma unroll
        for (int p = 0; p < 2; p++) {
            int ks = k0 + p * 16 + bk;
            const float* bp = (ks < 128) ? Broot + (size_t)ks * OUT
                                         : Bw + (size_t)(ks - 128) * OUT;
            bv[p] = *(const float4*)(bp + col0 + bn);
        }
        __syncthreads();
        #pragma unroll
        for (int p = 0; p < 4; p++) {
            unsigned* d = &As[p * 32 + ar][ak];
            d[0] = f2tf(av[p].x); d[1] = f2tf(av[p].y);
            d[2] = f2tf(av[p].z); d[3] = f2tf(av[p].w);
        }
        #pragma unroll
        for (int p = 0; p < 2; p++) {
            unsigned* d = &Bs[p * 16 + bk][bn];
            d[0] = f2tf(bv[p].x); d[1] = f2tf(bv[p].y);
            d[2] = f2tf(bv[p].z); d[3] = f2tf(bv[p].w);
        }
        __syncthreads();
        #pragma unroll
        for (int ks = 0; ks < 4; ks++) {
            int kk = ks * 8;
            unsigned a[2][4], b[4][2];
            #pragma unroll
            for (int t = 0; t < 2; t++) {
                int mb = wm * 32 + t * 16;
                // a0=(g,q) a1=(g+8,q) a2=(g,q+4) a3=(g+8,q+4)
                a[t][0] = As[mb + lg][kk + lq];
                a[t][1] = As[mb + lg + 8][kk + lq];
                a[t][2] = As[mb + lg][kk + lq + 4];
                a[t][3] = As[mb + lg + 8][kk + lq + 4];
            }
            #pragma unroll
            for (int j = 0; j < 4; j++) {
                int nb = wn * 32 + j * 8;
                b[j][0] = Bs[kk + lq][nb + lg];
                b[j][1] = Bs[kk + lq + 4][nb + lg];
            }
            #pragma unroll
            for (int t = 0; t < 2; t++)
                #pragma unroll
                for (int j = 0; j < 4; j++)
                    mma_tf32(acc[t][j], a[t], b[j]);
        }
        __syncthreads();
    }

    #pragma unroll
    for (int t = 0; t < 2; t++) {
        int r0 = row0 + wm * 32 + t * 16 + lg;
        #pragma unroll
        for (int j = 0; j < 4; j++) {
            int cb = col0 + wn * 32 + j * 8 + lq * 2;
            float bv0 = bias[cb], bv1 = bias[cb + 1];
            float v00 = acc[t][j][0] + bv0, v01 = acc[t][j][1] + bv1;
            float v10 = acc[t][j][2] + bv0, v11 = acc[t][j][3] + bv1;
            if (relu) {
                v00 = fmaxf(v00, 0.f); v01 = fmaxf(v01, 0.f);
                v10 = fmaxf(v10, 0.f); v11 = fmaxf(v11, 0.f);
            }
            if (r0 < M)
                *(float2*)(out + (size_t)r0 * ldo + cb) = make_float2(v00, v01);
            if (r0 + 8 < M)
                *(float2*)(out + (size_t)(r0 + 8) * ldo + cb) = make_float2(v10, v11);
        }
    }
}

// ---------------- host driver ------------------------------------------------
extern "C" void kernel_launch(void* const* d_in, const int* in_sizes, int n_in,
                              void* d_out, int out_size) {
    const float* x     = (const float*)d_in[0];
    const int*   ei    = (const int*)d_in[1];
    const int*   ea    = (const int*)d_in[2];
    const int*   batch = (const int*)d_in[3];
    const float* qe    = (const float*)d_in[4];
    const float* qnW   = (const float*)d_in[5];
    const float* qnb   = (const float*)d_in[6];
    const float* W0    = (const float*)d_in[7];
    const float* root0 = (const float*)d_in[8];
    const float* b0    = (const float*)d_in[9];
    const float* W1    = (const float*)d_in[10];
    const float* root1 = (const float*)d_in[11];
    const float* b1    = (const float*)d_in[12];
    const float* W2    = (const float*)d_in[13];
    const float* root2 = (const float*)d_in[14];
    const float* b2    = (const float*)d_in[15];
    const float* W3    = (const float*)d_in[16];
    const float* root3 = (const float*)d_in[17];
    const float* b3    = (const float*)d_in[18];

    int N = in_sizes[0] / 128;
    int E = in_sizes[2];
    const int* src = ei;
    const int* dst = ei + E;

    float *bufA = nullptr, *bufB = nullptr, *agg = nullptr;
    cudaGetSymbolAddress((void**)&bufA, g_bufA);
    cudaGetSymbolAddress((void**)&bufB, g_bufB);
    cudaGetSymbolAddress((void**)&agg, g_agg);

    // --- structure precompute ---
    q_kernel<<<16, 64>>>(qe, qnW, qnb);
    zero_cnt_kernel<<<(N * 4 + 255) / 256, 256>>>(N * 4);
    count_kernel<<<(E + 255) / 256, 256>>>(dst, ea, E);
    prep_kernel<<<(N + 255) / 256, 256>>>(N);
    scan_kernel<<<1, 1024>>>(N);
    fill_kernel<<<(E + 255) / 256, 256>>>(src, dst, ea, E);

    int nby = (N + 127) / 128;
    int agg_blocks = (N + 7) / 8;

    // --- layer 0: 128 -> 64 into bufA cols 0..63; q[batch] into cols 64..127
    aggx_kernel<<<agg_blocks, 256>>>(x, N);
    gemm_tc_kernel<<<dim3(1, nby), 256>>>(x, agg, root0, W0, b0, bufA, 128, N, 64, 1);
    qfill_kernel<<<(N * 64 + 255) / 256, 256>>>(batch, N);

    // --- layer 1: 128 -> 128 ---
    aggx_kernel<<<agg_blocks, 256>>>(bufA, N);
    gemm_tc_kernel<<<dim3(2, nby), 256>>>(bufA, agg, root1, W1, b1, bufB, 128, N, 128, 1);

    // --- layer 2: 128 -> 128 ---
    aggx_kernel<<<agg_blocks, 256>>>(bufB, N);
    gemm_tc_kernel<<<dim3(2, nby), 256>>>(bufB, agg, root2, W2, b2, bufA, 128, N, 128, 1);

    // --- layer 3: 128 -> 64, no relu, write d_out ---
    aggx_kernel<<<agg_blocks, 256>>>(bufA, N);
    gemm_tc_kernel<<<dim3(1, nby), 256>>>(bufA, agg, root3, W3, b3, (float*)d_out, 64, N, 64, 0);
}

// round 9
// speedup vs baseline: 1.1006x; 1.1006x over previous
#include <cuda_runtime.h>

// ---------------- problem constants (max sizes for static scratch) ----------
#define NN   50000
#define EE   800000

// ---------------- device scratch (no allocations allowed) -------------------
static __device__ float g_agg[(size_t)NN * 512];    // per-relation mean of neighbor feats (tf32-rounded)
static __device__ float g_bufA[(size_t)NN * 128];   // layer activations (ping, tf32-rounded)
static __device__ float g_bufB[(size_t)NN * 128];   // layer activations (pong, tf32-rounded)
static __device__ float g_wr[640 * 128];            // staged [root; W] weights, tf32-rounded
static __device__ float g_q[16 * 64];               // relu(question @ qn_W + qn_b), rounded
static __device__ int   g_cnt4[NN * 4];             // per-(node,relation) in-degree
static __device__ float g_icnt[NN * 4];             // 1/max(cnt,1)
static __device__ int   g_deg[NN];                  // total in-degree
static __device__ int   g_offs[NN + 1];             // CSR row offsets (by dst)
static __device__ int   g_cursor[NN];               // fill cursors
static __device__ int   g_csr[EE];                  // packed (src<<2)|etype, grouped by dst
static __device__ int   g_psum[64];                 // scan partials

// ---------------- helpers ----------------------------------------------------
__device__ __forceinline__ unsigned f2tf(float f) {
    unsigned u;
    asm("cvt.rna.tf32.f32 %0, %1;" : "=r"(u) : "f"(f));
    return u;
}
__device__ __forceinline__ float tfr(float f) { return __uint_as_float(f2tf(f)); }

__device__ __forceinline__ void cp16(void* smem, const void* g) {
    unsigned s = (unsigned)__cvta_generic_to_shared(smem);
    asm volatile("cp.async.ca.shared.global [%0], [%1], 16;\n" :: "r"(s), "l"(g));
}

// ---------------- small kernels ---------------------------------------------

// q = relu(question_embedding @ qn_W + qn_b)   [16 x 64], K = 768 (tf32-rounded)
__global__ void q_kernel(const float* __restrict__ qe,
                         const float* __restrict__ W,
                         const float* __restrict__ b) {
    int g = blockIdx.x;
    int j = threadIdx.x;
    const float* qr = qe + (size_t)g * 768;
    float s = b[j];
    #pragma unroll 4
    for (int k = 0; k < 768; k++)
        s = fmaf(qr[k], W[(size_t)k * 64 + j], s);
    g_q[g * 64 + j] = tfr(fmaxf(s, 0.f));
}

// round x into g_bufB (layer-0 activation home)
__global__ void xround_kernel(const float* __restrict__ x, int n) {
    int i = blockIdx.x * 256 + threadIdx.x;
    if (i < n) g_bufB[i] = tfr(x[i]);
}

__global__ void zero_cnt_kernel(int n4) {
    int i = blockIdx.x * 256 + threadIdx.x;
    if (i < n4) g_cnt4[i] = 0;
}

__global__ void count_kernel(const int* __restrict__ dst,
                             const int* __restrict__ et, int E) {
    int e = blockIdx.x * 256 + threadIdx.x;
    if (e < E) atomicAdd(&g_cnt4[dst[e] * 4 + et[e]], 1);
}

__global__ void prep_kernel(int n) {
    int i = blockIdx.x * 256 + threadIdx.x;
    if (i < n) {
        int d = 0;
        #pragma unroll
        for (int r = 0; r < 4; r++) {
            int c = g_cnt4[i * 4 + r];
            d += c;
            g_icnt[i * 4 + r] = 1.f / (float)(c > 0 ? c : 1);
        }
        g_deg[i] = d;
    }
}

// hierarchical scan: local exclusive + block partials
__global__ void scan1_kernel(int n) {
    __shared__ int s[1024];
    int t = threadIdx.x;
    int i = blockIdx.x * 1024 + t;
    int v = (i < n) ? g_deg[i] : 0;
    s[t] = v;
    __syncthreads();
    for (int off = 1; off < 1024; off <<= 1) {
        int x = (t >= off) ? s[t - off] : 0;
        __syncthreads();
        s[t] += x;
        __syncthreads();
    }
    if (i < n) g_offs[i] = s[t] - v;
    if (t == 1023) g_psum[blockIdx.x] = s[1023];
}

__global__ void scan2_kernel(int nb) {   // single block of 64
    __shared__ int s[64];
    int t = threadIdx.x;
    int v = (t < nb) ? g_psum[t] : 0;
    s[t] = v;
    __syncthreads();
    for (int off = 1; off < 64; off <<= 1) {
        int x = (t >= off) ? s[t - off] : 0;
        __syncthreads();
        s[t] += x;
        __syncthreads();
    }
    if (t < nb) g_psum[t] = s[t] - v;
}

__global__ void scan3_kernel(int n, int E) {
    int t = threadIdx.x;
    int i = blockIdx.x * 1024 + t;
    if (i < n) {
        int o = g_offs[i] + g_psum[blockIdx.x];
        g_offs[i] = o;
        g_cursor[i] = o;
    }
    if (i == 0) g_offs[n] = E;
}

__global__ void fill_kernel(const int* __restrict__ src,
                            const int* __restrict__ dst,
                            const int* __restrict__ et, int E) {
    int e = blockIdx.x * 256 + threadIdx.x;
    if (e < E) {
        int d = dst[e];
        int pos = atomicAdd(&g_cursor[d], 1);
        g_csr[pos] = (src[e] << 2) | et[e];
    }
}

// comb[:, 64:128] = q[batch[i]]  (g_q already rounded)
__global__ void qfill_kernel(const int* __restrict__ batch, int n) {
    int t = blockIdx.x * 256 + threadIdx.x;
    if (t < n * 64) {
        int i = t >> 6, j = t & 63;
        g_bufA[(size_t)i * 128 + 64 + j] = g_q[batch[i] * 64 + j];
    }
}

// stage + tf32-round weights: g_wr[640][OUT] = [root(128 rows); W(512 rows)]
__global__ void wround_kernel(const float* __restrict__ root,
                              const float* __restrict__ W, int OUT) {
    int idx = blockIdx.x * 256 + threadIdx.x;
    if (idx < 640 * OUT) {
        int k = idx / OUT, o = idx - k * OUT;
        float v = (k < 128) ? root[(size_t)k * OUT + o]
                            : W[(size_t)(k - 128) * OUT + o];
        g_wr[idx] = tfr(v);
    }
}

// ---------------- aggregation in INPUT space: warp per node -----------------
__global__ void __launch_bounds__(256) aggx_kernel(const float* __restrict__ act,
                                                   int M) {
    int w = (blockIdx.x * 256 + threadIdx.x) >> 5;
    int lane = threadIdx.x & 31;
    if (w >= M) return;
    float a0[4] = {0,0,0,0}, a1[4] = {0,0,0,0};
    float a2[4] = {0,0,0,0}, a3[4] = {0,0,0,0};
    int beg = g_offs[w], end = g_offs[w + 1];
    for (int e = beg; e < end; e++) {
        int p = g_csr[e];
        float4 v = *(const float4*)(act + (size_t)(p >> 2) * 128 + lane * 4);
        int r = p & 3;
        if (r == 0)      { a0[0]+=v.x; a0[1]+=v.y; a0[2]+=v.z; a0[3]+=v.w; }
        else if (r == 1) { a1[0]+=v.x; a1[1]+=v.y; a1[2]+=v.z; a1[3]+=v.w; }
        else if (r == 2) { a2[0]+=v.x; a2[1]+=v.y; a2[2]+=v.z; a2[3]+=v.w; }
        else             { a3[0]+=v.x; a3[1]+=v.y; a3[2]+=v.z; a3[3]+=v.w; }
    }
    const float* icn = g_icnt + w * 4;
    float s0 = icn[0], s1 = icn[1], s2 = icn[2], s3 = icn[3];
    float* o = g_agg + (size_t)w * 512 + lane * 4;
    *(float4*)(o)       = make_float4(tfr(a0[0]*s0), tfr(a0[1]*s0), tfr(a0[2]*s0), tfr(a0[3]*s0));
    *(float4*)(o + 128) = make_float4(tfr(a1[0]*s1), tfr(a1[1]*s1), tfr(a1[2]*s1), tfr(a1[3]*s1));
    *(float4*)(o + 256) = make_float4(tfr(a2[0]*s2), tfr(a2[1]*s2), tfr(a2[2]*s2), tfr(a2[3]*s2));
    *(float4*)(o + 384) = make_float4(tfr(a3[0]*s3), tfr(a3[1]*s3), tfr(a3[2]*s3), tfr(a3[3]*s3));
}

// ---------------- TF32 GEMM: 3-stage cp.async pipeline ----------------------
// out[M,OUT] = [A0 | A1] @ g_wr[640,OUT], fused bias (+relu +tf32-round).
// All operands pre-rounded to tf32 -> mma fed raw fp32 bits (no cvt in loop).
// BM=128, BN=64, BK=16, 8 warps (4x2), warp tile 32x32, mma m16n8k8.

__device__ __forceinline__ void mma_tf32(float* c, const unsigned* a, const unsigned* b) {
    asm volatile("mma.sync.aligned.m16n8k8.row.col.f32.tf32.tf32.f32 "
                 "{%0,%1,%2,%3}, {%4,%5,%6,%7}, {%8,%9}, {%0,%1,%2,%3};"
                 : "+f"(c[0]), "+f"(c[1]), "+f"(c[2]), "+f"(c[3])
                 : "r"(a[0]), "r"(a[1]), "r"(a[2]), "r"(a[3]),
                   "r"(b[0]), "r"(b[1]));
}

__global__ void __launch_bounds__(256) gemm_tc_kernel(
        const float* __restrict__ A0, const float* __restrict__ A1,
        const float* __restrict__ bias,
        float* __restrict__ out, int ldo, int M, int OUT, int relu) {
    __shared__ float As[3][128][20];   // [m][k], ld 20 -> conflict-free, 16B-aligned rows
    __shared__ float Bs[3][16][72];    // [k][n], ld 72 -> conflict-free, 16B-aligned rows
    int tid = threadIdx.x;
    int warp = tid >> 5, lane = tid & 31;
    int wm = warp >> 1, wn = warp & 1;
    int lg = lane >> 2, lq = lane & 3;
    int row0 = blockIdx.y * 128, col0 = blockIdx.x * 64;

    float acc[2][4][4];
    #pragma unroll
    for (int t = 0; t < 2; t++)
        #pragma unroll
        for (int j = 0; j < 4; j++)
            #pragma unroll
            for (int v = 0; v < 4; v++) acc[t][j][v] = 0.f;

    // per-thread copy assignments
    int am0 = tid >> 2;               // A chunk 1: row
    int am1 = 64 + (tid >> 2);        // A chunk 2: row
    int akq = (tid & 3) * 4;          // A: k quad
    int bkr = tid >> 4;               // B: k row (0..15)
    int bn4 = (tid & 15) * 4;         // B: n quad
    int r0c = min(row0 + am0, M - 1);
    int r1c = min(row0 + am1, M - 1);

    const int NCHUNK = 40;            // 640 / 16

    auto issue = [&](int i, int st) {
        int k0 = i * 16;
        const float *s0, *s1;
        if (k0 < 128) {
            s0 = A0 + (size_t)r0c * 128 + k0 + akq;
            s1 = A0 + (size_t)r1c * 128 + k0 + akq;
        } else {
            s0 = A1 + (size_t)r0c * 512 + (k0 - 128) + akq;
            s1 = A1 + (size_t)r1c * 512 + (k0 - 128) + akq;
        }
        cp16(&As[st][am0][akq], s0);
        cp16(&As[st][am1][akq], s1);
        cp16(&Bs[st][bkr][bn4], g_wr + (size_t)(k0 + bkr) * OUT + col0 + bn4);
        asm volatile("cp.async.commit_group;\n");
    };

    issue(0, 0);
    issue(1, 1);

    for (int i = 0; i < NCHUNK; i++) {
        if (i + 1 < NCHUNK) asm volatile("cp.async.wait_group 1;\n");
        else                asm volatile("cp.async.wait_group 0;\n");
        __syncthreads();
        int st = i % 3;
        #pragma unroll
        for (int ks = 0; ks < 2; ks++) {
            int kk = ks * 8;
            unsigned a[2][4], b[4][2];
            #pragma unroll
            for (int t = 0; t < 2; t++) {
                int mb = wm * 32 + t * 16;
                a[t][0] = __float_as_uint(As[st][mb + lg][kk + lq]);
                a[t][1] = __float_as_uint(As[st][mb + lg + 8][kk + lq]);
                a[t][2] = __float_as_uint(As[st][mb + lg][kk + lq + 4]);
                a[t][3] = __float_as_uint(As[st][mb + lg + 8][kk + lq + 4]);
            }
            #pragma unroll
            for (int j = 0; j < 4; j++) {
                int nb = wn * 32 + j * 8;
                b[j][0] = __float_as_uint(Bs[st][kk + lq][nb + lg]);
                b[j][1] = __float_as_uint(Bs[st][kk + lq + 4][nb + lg]);
            }
            #pragma unroll
            for (int t = 0; t < 2; t++)
                #pragma unroll
                for (int j = 0; j < 4; j++)
                    mma_tf32(acc[t][j], a[t], b[j]);
        }
        if (i + 2 < NCHUNK) issue(i + 2, (i + 2) % 3);
    }

    #pragma unroll
    for (int t = 0; t < 2; t++) {
        int r0 = row0 + wm * 32 + t * 16 + lg;
        #pragma unroll
        for (int j = 0; j < 4; j++) {
            int cb = col0 + wn * 32 + j * 8 + lq * 2;
            float bv0 = bias[cb], bv1 = bias[cb + 1];
            float v00 = acc[t][j][0] + bv0, v01 = acc[t][j][1] + bv1;
            float v10 = acc[t][j][2] + bv0, v11 = acc[t][j][3] + bv1;
            if (relu) {   // hidden layers: relu + round for next layer's tf32 feed
                v00 = tfr(fmaxf(v00, 0.f)); v01 = tfr(fmaxf(v01, 0.f));
                v10 = tfr(fmaxf(v10, 0.f)); v11 = tfr(fmaxf(v11, 0.f));
            }
            if (r0 < M)
                *(float2*)(out + (size_t)r0 * ldo + cb) = make_float2(v00, v01);
            if (r0 + 8 < M)
                *(float2*)(out + (size_t)(r0 + 8) * ldo + cb) = make_float2(v10, v11);
        }
    }
}

// ---------------- host driver ------------------------------------------------
extern "C" void kernel_launch(void* const* d_in, const int* in_sizes, int n_in,
                              void* d_out, int out_size) {
    const float* x     = (const float*)d_in[0];
    const int*   ei    = (const int*)d_in[1];
    const int*   ea    = (const int*)d_in[2];
    const int*   batch = (const int*)d_in[3];
    const float* qe    = (const float*)d_in[4];
    const float* qnW   = (const float*)d_in[5];
    const float* qnb   = (const float*)d_in[6];
    const float* W0    = (const float*)d_in[7];
    const float* root0 = (const float*)d_in[8];
    const float* b0    = (const float*)d_in[9];
    const float* W1    = (const float*)d_in[10];
    const float* root1 = (const float*)d_in[11];
    const float* b1    = (const float*)d_in[12];
    const float* W2    = (const float*)d_in[13];
    const float* root2 = (const float*)d_in[14];
    const float* b2    = (const float*)d_in[15];
    const float* W3    = (const float*)d_in[16];
    const float* root3 = (const float*)d_in[17];
    const float* b3    = (const float*)d_in[18];

    int N = in_sizes[0] / 128;
    int E = in_sizes[2];
    const int* src = ei;
    const int* dst = ei + E;

    float *bufA = nullptr, *bufB = nullptr, *agg = nullptr;
    cudaGetSymbolAddress((void**)&bufA, g_bufA);
    cudaGetSymbolAddress((void**)&bufB, g_bufB);
    cudaGetSymbolAddress((void**)&agg, g_agg);

    int nb1024 = (N + 1023) / 1024;

    // --- structure precompute + input rounding ---
    q_kernel<<<16, 64>>>(qe, qnW, qnb);
    xround_kernel<<<(N * 128 + 255) / 256, 256>>>(x, N * 128);
    zero_cnt_kernel<<<(N * 4 + 255) / 256, 256>>>(N * 4);
    count_kernel<<<(E + 255) / 256, 256>>>(dst, ea, E);
    prep_kernel<<<(N + 255) / 256, 256>>>(N);
    scan1_kernel<<<nb1024, 1024>>>(N);
    scan2_kernel<<<1, 64>>>(nb1024);
    scan3_kernel<<<nb1024, 1024>>>(N, E);
    fill_kernel<<<(E + 255) / 256, 256>>>(src, dst, ea, E);

    int nby = (N + 127) / 128;
    int agg_blocks = (N + 7) / 8;

    // --- layer 0: 128 -> 64 into bufA cols 0..63; q[batch] into cols 64..127
    wround_kernel<<<(640 * 64 + 255) / 256, 256>>>(root0, W0, 64);
    aggx_kernel<<<agg_blocks, 256>>>(bufB, N);                 // bufB = rounded x
    gemm_tc_kernel<<<dim3(1, nby), 256>>>(bufB, agg, b0, bufA, 128, N, 64, 1);
    qfill_kernel<<<(N * 64 + 255) / 256, 256>>>(batch, N);

    // --- layer 1: 128 -> 128 ---
    wround_kernel<<<(640 * 128 + 255) / 256, 256>>>(root1, W1, 128);
    aggx_kernel<<<agg_blocks, 256>>>(bufA, N);
    gemm_tc_kernel<<<dim3(2, nby), 256>>>(bufA, agg, b1, bufB, 128, N, 128, 1);

    // --- layer 2: 128 -> 128 ---
    wround_kernel<<<(640 * 128 + 255) / 256, 256>>>(root2, W2, 128);
    aggx_kernel<<<agg_blocks, 256>>>(bufB, N);
    gemm_tc_kernel<<<dim3(2, nby), 256>>>(bufB, agg, b2, bufA, 128, N, 128, 1);

    // --- layer 3: 128 -> 64, no relu/round, write d_out ---
    wround_kernel<<<(640 * 64 + 255) / 256, 256>>>(root3, W3, 64);
    aggx_kernel<<<agg_blocks, 256>>>(bufA, N);
    gemm_tc_kernel<<<dim3(1, nby), 256>>>(bufA, agg, b3, (float*)d_out, 64, N, 64, 0);
}

// round 13
// speedup vs baseline: 1.1475x; 1.0426x over previous
#include <cuda_runtime.h>

// ---------------- problem constants (max sizes for static scratch) ----------
#define NN   50000
#define EE   800000

// ---------------- device scratch (no allocations allowed) -------------------
static __device__ float g_agg[(size_t)NN * 512];    // per-relation mean of neighbor feats (tf32-rounded)
static __device__ float g_bufA[(size_t)NN * 128];   // layer activations (ping, tf32-rounded)
static __device__ float g_bufB[(size_t)NN * 128];   // layer activations (pong, tf32-rounded)
static __device__ float g_wr[640 * 128];            // staged [root; W] weights, tf32-rounded
static __device__ float g_q[16 * 64];               // relu(question @ qn_W + qn_b), rounded
static __device__ int   g_cnt4[NN * 4];             // per-(node,relation) in-degree
static __device__ float g_icnt[NN * 4];             // 1/max(cnt,1)
static __device__ int   g_deg[NN];                  // total in-degree
static __device__ int   g_offs[NN + 1];             // CSR row offsets (by dst)
static __device__ int   g_cursor[NN];               // fill cursors
static __device__ int   g_csr[EE];                  // packed (src<<2)|etype, grouped by dst
static __device__ int   g_psum[64];                 // scan partials

// ---------------- helpers ----------------------------------------------------
__device__ __forceinline__ unsigned f2tf(float f) {
    unsigned u;
    asm("cvt.rna.tf32.f32 %0, %1;" : "=r"(u) : "f"(f));
    return u;
}
__device__ __forceinline__ float tfr(float f) { return __uint_as_float(f2tf(f)); }

__device__ __forceinline__ void cp16(void* smem, const void* g) {
    unsigned s = (unsigned)__cvta_generic_to_shared(smem);
    asm volatile("cp.async.ca.shared.global [%0], [%1], 16;\n" :: "r"(s), "l"(g));
}

__device__ __forceinline__ void mma_tf32(float* c, const unsigned* a, const unsigned* b) {
    asm volatile("mma.sync.aligned.m16n8k8.row.col.f32.tf32.tf32.f32 "
                 "{%0,%1,%2,%3}, {%4,%5,%6,%7}, {%8,%9}, {%0,%1,%2,%3};"
                 : "+f"(c[0]), "+f"(c[1]), "+f"(c[2]), "+f"(c[3])
                 : "r"(a[0]), "r"(a[1]), "r"(a[2]), "r"(a[3]),
                   "r"(b[0]), "r"(b[1]));
}

// ---------------- small kernels ---------------------------------------------

// q = relu(question_embedding @ qn_W + qn_b)   [16 x 64], K = 768 (tf32-rounded)
__global__ void q_kernel(const float* __restrict__ qe,
                         const float* __restrict__ W,
                         const float* __restrict__ b) {
    int g = blockIdx.x;
    int j = threadIdx.x;
    const float* qr = qe + (size_t)g * 768;
    float s = b[j];
    #pragma unroll 4
    for (int k = 0; k < 768; k++)
        s = fmaf(qr[k], W[(size_t)k * 64 + j], s);
    g_q[g * 64 + j] = tfr(fmaxf(s, 0.f));
}

// round x into g_bufB (layer-0 activation home)
__global__ void xround_kernel(const float* __restrict__ x, int n) {
    int i = blockIdx.x * 256 + threadIdx.x;
    if (i < n) g_bufB[i] = tfr(x[i]);
}

__global__ void zero_cnt_kernel(int n4) {
    int i = blockIdx.x * 256 + threadIdx.x;
    if (i < n4) g_cnt4[i] = 0;
}

__global__ void count_kernel(const int* __restrict__ dst,
                             const int* __restrict__ et, int E) {
    int e = blockIdx.x * 256 + threadIdx.x;
    if (e < E) atomicAdd(&g_cnt4[dst[e] * 4 + et[e]], 1);
}

__global__ void prep_kernel(int n) {
    int i = blockIdx.x * 256 + threadIdx.x;
    if (i < n) {
        int d = 0;
        #pragma unroll
        for (int r = 0; r < 4; r++) {
            int c = g_cnt4[i * 4 + r];
            d += c;
            g_icnt[i * 4 + r] = 1.f / (float)(c > 0 ? c : 1);
        }
        g_deg[i] = d;
    }
}

// hierarchical scan
__global__ void scan1_kernel(int n) {
    __shared__ int s[1024];
    int t = threadIdx.x;
    int i = blockIdx.x * 1024 + t;
    int v = (i < n) ? g_deg[i] : 0;
    s[t] = v;
    __syncthreads();
    for (int off = 1; off < 1024; off <<= 1) {
        int x = (t >= off) ? s[t - off] : 0;
        __syncthreads();
        s[t] += x;
        __syncthreads();
    }
    if (i < n) g_offs[i] = s[t] - v;
    if (t == 1023) g_psum[blockIdx.x] = s[1023];
}

__global__ void scan2_kernel(int nb) {
    __shared__ int s[64];
    int t = threadIdx.x;
    int v = (t < nb) ? g_psum[t] : 0;
    s[t] = v;
    __syncthreads();
    for (int off = 1; off < 64; off <<= 1) {
        int x = (t >= off) ? s[t - off] : 0;
        __syncthreads();
        s[t] += x;
        __syncthreads();
    }
    if (t < nb) g_psum[t] = s[t] - v;
}

__global__ void scan3_kernel(int n, int E) {
    int t = threadIdx.x;
    int i = blockIdx.x * 1024 + t;
    if (i < n) {
        int o = g_offs[i] + g_psum[blockIdx.x];
        g_offs[i] = o;
        g_cursor[i] = o;
    }
    if (i == 0) g_offs[n] = E;
}

__global__ void fill_kernel(const int* __restrict__ src,
                            const int* __restrict__ dst,
                            const int* __restrict__ et, int E) {
    int e = blockIdx.x * 256 + threadIdx.x;
    if (e < E) {
        int d = dst[e];
        int pos = atomicAdd(&g_cursor[d], 1);
        g_csr[pos] = (src[e] << 2) | et[e];
    }
}

// comb[:, 64:128] = q[batch[i]]  (g_q already rounded)
__global__ void qfill_kernel(const int* __restrict__ batch, int n) {
    int t = blockIdx.x * 256 + threadIdx.x;
    if (t < n * 64) {
        int i = t >> 6, j = t & 63;
        g_bufA[(size_t)i * 128 + 64 + j] = g_q[batch[i] * 64 + j];
    }
}

// stage + tf32-round weights: g_wr[640][OUT] = [root(128 rows); W(512 rows)]
__global__ void wround_kernel(const float* __restrict__ root,
                              const float* __restrict__ W, int OUT) {
    int idx = blockIdx.x * 256 + threadIdx.x;
    if (idx < 640 * OUT) {
        int k = idx / OUT, o = idx - k * OUT;
        float v = (k < 128) ? root[(size_t)k * OUT + o]
                            : W[(size_t)(k - 128) * OUT + o];
        g_wr[idx] = tfr(v);
    }
}

// ---------------- aggregation in INPUT space: warp per node, 2x unroll ------
__global__ void __launch_bounds__(256) aggx_kernel(const float* __restrict__ act,
                                                   int M) {
    int w = (blockIdx.x * 256 + threadIdx.x) >> 5;
    int lane = threadIdx.x & 31;
    if (w >= M) return;
    float a0[4] = {0,0,0,0}, a1[4] = {0,0,0,0};
    float a2[4] = {0,0,0,0}, a3[4] = {0,0,0,0};
    int beg = g_offs[w], end = g_offs[w + 1];
    int e = beg;
    for (; e + 1 < end; e += 2) {
        int p0 = g_csr[e], p1 = g_csr[e + 1];
        float4 v0 = *(const float4*)(act + (size_t)(p0 >> 2) * 128 + lane * 4);
        float4 v1 = *(const float4*)(act + (size_t)(p1 >> 2) * 128 + lane * 4);
        int r0 = p0 & 3;
        if (r0 == 0)      { a0[0]+=v0.x; a0[1]+=v0.y; a0[2]+=v0.z; a0[3]+=v0.w; }
        else if (r0 == 1) { a1[0]+=v0.x; a1[1]+=v0.y; a1[2]+=v0.z; a1[3]+=v0.w; }
        else if (r0 == 2) { a2[0]+=v0.x; a2[1]+=v0.y; a2[2]+=v0.z; a2[3]+=v0.w; }
        else              { a3[0]+=v0.x; a3[1]+=v0.y; a3[2]+=v0.z; a3[3]+=v0.w; }
        int r1 = p1 & 3;
        if (r1 == 0)      { a0[0]+=v1.x; a0[1]+=v1.y; a0[2]+=v1.z; a0[3]+=v1.w; }
        else if (r1 == 1) { a1[0]+=v1.x; a1[1]+=v1.y; a1[2]+=v1.z; a1[3]+=v1.w; }
        else if (r1 == 2) { a2[0]+=v1.x; a2[1]+=v1.y; a2[2]+=v1.z; a2[3]+=v1.w; }
        else              { a3[0]+=v1.x; a3[1]+=v1.y; a3[2]+=v1.z; a3[3]+=v1.w; }
    }
    if (e < end) {
        int p = g_csr[e];
        float4 v = *(const float4*)(act + (size_t)(p >> 2) * 128 + lane * 4);
        int r = p & 3;
        if (r == 0)      { a0[0]+=v.x; a0[1]+=v.y; a0[2]+=v.z; a0[3]+=v.w; }
        else if (r == 1) { a1[0]+=v.x; a1[1]+=v.y; a1[2]+=v.z; a1[3]+=v.w; }
        else if (r == 2) { a2[0]+=v.x; a2[1]+=v.y; a2[2]+=v.z; a2[3]+=v.w; }
        else             { a3[0]+=v.x; a3[1]+=v.y; a3[2]+=v.z; a3[3]+=v.w; }
    }
    const float* icn = g_icnt + w * 4;
    float s0 = icn[0], s1 = icn[1], s2 = icn[2], s3 = icn[3];
    float* o = g_agg + (size_t)w * 512 + lane * 4;
    *(float4*)(o)       = make_float4(tfr(a0[0]*s0), tfr(a0[1]*s0), tfr(a0[2]*s0), tfr(a0[3]*s0));
    *(float4*)(o + 128) = make_float4(tfr(a1[0]*s1), tfr(a1[1]*s1), tfr(a1[2]*s1), tfr(a1[3]*s1));
    *(float4*)(o + 256) = make_float4(tfr(a2[0]*s2), tfr(a2[1]*s2), tfr(a2[2]*s2), tfr(a2[3]*s2));
    *(float4*)(o + 384) = make_float4(tfr(a3[0]*s3), tfr(a3[1]*s3), tfr(a3[2]*s3), tfr(a3[3]*s3));
}

// ---------------- TF32 GEMM BN=64 (OUT=64 layers): 3-stage pipeline ---------
__global__ void __launch_bounds__(256) gemm_tc_kernel(
        const float* __restrict__ A0, const float* __restrict__ A1,
        const float* __restrict__ bias,
        float* __restrict__ out, int ldo, int M, int OUT, int relu) {
    __shared__ float As[3][128][20];
    __shared__ float Bs[3][16][72];
    int tid = threadIdx.x;
    int warp = tid >> 5, lane = tid & 31;
    int wm = warp >> 1, wn = warp & 1;
    int lg = lane >> 2, lq = lane & 3;
    int row0 = blockIdx.y * 128, col0 = blockIdx.x * 64;

    float acc[2][4][4];
    #pragma unroll
    for (int t = 0; t < 2; t++)
        #pragma unroll
        for (int j = 0; j < 4; j++)
            #pragma unroll
            for (int v = 0; v < 4; v++) acc[t][j][v] = 0.f;

    int am0 = tid >> 2;
    int am1 = 64 + (tid >> 2);
    int akq = (tid & 3) * 4;
    int bkr = tid >> 4;
    int bn4 = (tid & 15) * 4;
    int r0c = min(row0 + am0, M - 1);
    int r1c = min(row0 + am1, M - 1);

    const int NCHUNK = 40;

    auto issue = [&](int i, int st) {
        int k0 = i * 16;
        const float *s0, *s1;
        if (k0 < 128) {
            s0 = A0 + (size_t)r0c * 128 + k0 + akq;
            s1 = A0 + (size_t)r1c * 128 + k0 + akq;
        } else {
            s0 = A1 + (size_t)r0c * 512 + (k0 - 128) + akq;
            s1 = A1 + (size_t)r1c * 512 + (k0 - 128) + akq;
        }
        cp16(&As[st][am0][akq], s0);
        cp16(&As[st][am1][akq], s1);
        cp16(&Bs[st][bkr][bn4], g_wr + (size_t)(k0 + bkr) * OUT + col0 + bn4);
        asm volatile("cp.async.commit_group;\n");
    };

    issue(0, 0);
    issue(1, 1);

    for (int i = 0; i < NCHUNK; i++) {
        if (i + 1 < NCHUNK) asm volatile("cp.async.wait_group 1;\n");
        else                asm volatile("cp.async.wait_group 0;\n");
        __syncthreads();
        int st = i % 3;
        #pragma unroll
        for (int ks = 0; ks < 2; ks++) {
            int kk = ks * 8;
            unsigned a[2][4], b[4][2];
            #pragma unroll
            for (int t = 0; t < 2; t++) {
                int mb = wm * 32 + t * 16;
                a[t][0] = __float_as_uint(As[st][mb + lg][kk + lq]);
                a[t][1] = __float_as_uint(As[st][mb + lg + 8][kk + lq]);
                a[t][2] = __float_as_uint(As[st][mb + lg][kk + lq + 4]);
                a[t][3] = __float_as_uint(As[st][mb + lg + 8][kk + lq + 4]);
            }
            #pragma unroll
            for (int j = 0; j < 4; j++) {
                int nb = wn * 32 + j * 8;
                b[j][0] = __float_as_uint(Bs[st][kk + lq][nb + lg]);
                b[j][1] = __float_as_uint(Bs[st][kk + lq + 4][nb + lg]);
            }
            #pragma unroll
            for (int t = 0; t < 2; t++)
                #pragma unroll
                for (int j = 0; j < 4; j++)
                    mma_tf32(acc[t][j], a[t], b[j]);
        }
        if (i + 2 < NCHUNK) issue(i + 2, (i + 2) % 3);
    }

    #pragma unroll
    for (int t = 0; t < 2; t++) {
        int r0 = row0 + wm * 32 + t * 16 + lg;
        #pragma unroll
        for (int j = 0; j < 4; j++) {
            int cb = col0 + wn * 32 + j * 8 + lq * 2;
            float bv0 = bias[cb], bv1 = bias[cb + 1];
            float v00 = acc[t][j][0] + bv0, v01 = acc[t][j][1] + bv1;
            float v10 = acc[t][j][2] + bv0, v11 = acc[t][j][3] + bv1;
            if (relu) {
                v00 = tfr(fmaxf(v00, 0.f)); v01 = tfr(fmaxf(v01, 0.f));
                v10 = tfr(fmaxf(v10, 0.f)); v11 = tfr(fmaxf(v11, 0.f));
            }
            if (r0 < M)
                *(float2*)(out + (size_t)r0 * ldo + cb) = make_float2(v00, v01);
            if (r0 + 8 < M)
                *(float2*)(out + (size_t)(r0 + 8) * ldo + cb) = make_float2(v10, v11);
        }
    }
}

// ---------------- TF32 GEMM BN=128 (OUT=128 layers): 2-stage, A read once ---
__global__ void __launch_bounds__(256) gemm128_kernel(
        const float* __restrict__ A0, const float* __restrict__ A1,
        const float* __restrict__ bias,
        float* __restrict__ out, int M, int relu) {
    __shared__ float As[2][128][20];
    __shared__ float Bs[2][16][136];
    const int OUT = 128;
    int tid = threadIdx.x;
    int warp = tid >> 5, lane = tid & 31;
    int wm = warp >> 1, wn = warp & 1;          // warp tile 32 x 64
    int lg = lane >> 2, lq = lane & 3;
    int row0 = blockIdx.y * 128;

    float acc[2][8][4];
    #pragma unroll
    for (int t = 0; t < 2; t++)
        #pragma unroll
        for (int j = 0; j < 8; j++)
            #pragma unroll
            for (int v = 0; v < 4; v++) acc[t][j][v] = 0.f;

    int am0 = tid >> 2;
    int am1 = 64 + (tid >> 2);
    int akq = (tid & 3) * 4;
    int bkr = tid >> 4;
    int bn4 = (tid & 15) * 4;
    int r0c = min(row0 + am0, M - 1);
    int r1c = min(row0 + am1, M - 1);

    const int NCHUNK = 40;

    auto issue = [&](int i, int st) {
        int k0 = i * 16;
        const float *s0, *s1;
        if (k0 < 128) {
            s0 = A0 + (size_t)r0c * 128 + k0 + akq;
            s1 = A0 + (size_t)r1c * 128 + k0 + akq;
        } else {
            s0 = A1 + (size_t)r0c * 512 + (k0 - 128) + akq;
            s1 = A1 + (size_t)r1c * 512 + (k0 - 128) + akq;
        }
        cp16(&As[st][am0][akq], s0);
        cp16(&As[st][am1][akq], s1);
        const float* bp = g_wr + (size_t)(k0 + bkr) * OUT;
        cp16(&Bs[st][bkr][bn4], bp + bn4);
        cp16(&Bs[st][bkr][bn4 + 64], bp + bn4 + 64);
        asm volatile("cp.async.commit_group;\n");
    };

    issue(0, 0);

    for (int i = 0; i < NCHUNK; i++) {
        asm volatile("cp.async.wait_group 0;\n");
        __syncthreads();
        if (i + 1 < NCHUNK) issue(i + 1, (i + 1) & 1);
        int st = i & 1;
        #pragma unroll
        for (int ks = 0; ks < 2; ks++) {
            int kk = ks * 8;
            unsigned a[2][4], b[8][2];
            #pragma unroll
            for (int t = 0; t < 2; t++) {
                int mb = wm * 32 + t * 16;
                a[t][0] = __float_as_uint(As[st][mb + lg][kk + lq]);
                a[t][1] = __float_as_uint(As[st][mb + lg + 8][kk + lq]);
                a[t][2] = __float_as_uint(As[st][mb + lg][kk + lq + 4]);
                a[t][3] = __float_as_uint(As[st][mb + lg + 8][kk + lq + 4]);
            }
            #pragma unroll
            for (int j = 0; j < 8; j++) {
                int nb = wn * 64 + j * 8;
                b[j][0] = __float_as_uint(Bs[st][kk + lq][nb + lg]);
                b[j][1] = __float_as_uint(Bs[st][kk + lq + 4][nb + lg]);
            }
            #pragma unroll
            for (int t = 0; t < 2; t++)
                #pragma unroll
                for (int j = 0; j < 8; j++)
                    mma_tf32(acc[t][j], a[t], b[j]);
        }
    }

    #pragma unroll
    for (int t = 0; t < 2; t++) {
        int r0 = row0 + wm * 32 + t * 16 + lg;
        #pragma unroll
        for (int j = 0; j < 8; j++) {
            int cb = wn * 64 + j * 8 + lq * 2;
            float bv0 = bias[cb], bv1 = bias[cb + 1];
            float v00 = acc[t][j][0] + bv0, v01 = acc[t][j][1] + bv1;
            float v10 = acc[t][j][2] + bv0, v11 = acc[t][j][3] + bv1;
            if (relu) {
                v00 = tfr(fmaxf(v00, 0.f)); v01 = tfr(fmaxf(v01, 0.f));
                v10 = tfr(fmaxf(v10, 0.f)); v11 = tfr(fmaxf(v11, 0.f));
            }
            if (r0 < M)
                *(float2*)(out + (size_t)r0 * OUT + cb) = make_float2(v00, v01);
            if (r0 + 8 < M)
                *(float2*)(out + (size_t)(r0 + 8) * OUT + cb) = make_float2(v10, v11);
        }
    }
}

// ---------------- host driver ------------------------------------------------
extern "C" void kernel_launch(void* const* d_in, const int* in_sizes, int n_in,
                              void* d_out, int out_size) {
    const float* x     = (const float*)d_in[0];
    const int*   ei    = (const int*)d_in[1];
    const int*   ea    = (const int*)d_in[2];
    const int*   batch = (const int*)d_in[3];
    const float* qe    = (const float*)d_in[4];
    const float* qnW   = (const float*)d_in[5];
    const float* qnb   = (const float*)d_in[6];
    const float* W0    = (const float*)d_in[7];
    const float* root0 = (const float*)d_in[8];
    const float* b0    = (const float*)d_in[9];
    const float* W1    = (const float*)d_in[10];
    const float* root1 = (const float*)d_in[11];
    const float* b1    = (const float*)d_in[12];
    const float* W2    = (const float*)d_in[13];
    const float* root2 = (const float*)d_in[14];
    const float* b2    = (const float*)d_in[15];
    const float* W3    = (const float*)d_in[16];
    const float* root3 = (const float*)d_in[17];
    const float* b3    = (const float*)d_in[18];

    int N = in_sizes[0] / 128;
    int E = in_sizes[2];
    const int* src = ei;
    const int* dst = ei + E;

    float *bufA = nullptr, *bufB = nullptr, *agg = nullptr;
    cudaGetSymbolAddress((void**)&bufA, g_bufA);
    cudaGetSymbolAddress((void**)&bufB, g_bufB);
    cudaGetSymbolAddress((void**)&agg, g_agg);

    int nb1024 = (N + 1023) / 1024;

    // --- structure precompute + input rounding ---
    q_kernel<<<16, 64>>>(qe, qnW, qnb);
    xround_kernel<<<(N * 128 + 255) / 256, 256>>>(x, N * 128);
    zero_cnt_kernel<<<(N * 4 + 255) / 256, 256>>>(N * 4);
    count_kernel<<<(E + 255) / 256, 256>>>(dst, ea, E);
    prep_kernel<<<(N + 255) / 256, 256>>>(N);
    scan1_kernel<<<nb1024, 1024>>>(N);
    scan2_kernel<<<1, 64>>>(nb1024);
    scan3_kernel<<<nb1024, 1024>>>(N, E);
    fill_kernel<<<(E + 255) / 256, 256>>>(src, dst, ea, E);

    int nby = (N + 127) / 128;
    int agg_blocks = (N + 7) / 8;

    // --- layer 0: 128 -> 64 into bufA cols 0..63; q[batch] into cols 64..127
    wround_kernel<<<(640 * 64 + 255) / 256, 256>>>(root0, W0, 64);
    aggx_kernel<<<agg_blocks, 256>>>(bufB, N);                 // bufB = rounded x
    gemm_tc_kernel<<<dim3(1, nby), 256>>>(bufB, agg, b0, bufA, 128, N, 64, 1);
    qfill_kernel<<<(N * 64 + 255) / 256, 256>>>(batch, N);

    // --- layer 1: 128 -> 128 ---
    wround_kernel<<<(640 * 128 + 255) / 256, 256>>>(root1, W1, 128);
    aggx_kernel<<<agg_blocks, 256>>>(bufA, N);
    gemm128_kernel<<<dim3(1, nby), 256>>>(bufA, agg, b1, bufB, N, 1);

    // --- layer 2: 128 -> 128 ---
    wround_kernel<<<(640 * 128 + 255) / 256, 256>>>(root2, W2, 128);
    aggx_kernel<<<agg_blocks, 256>>>(bufB, N);
    gemm128_kernel<<<dim3(1, nby), 256>>>(bufB, agg, b2, bufA, N, 1);

    // --- layer 3: 128 -> 64, no relu/round, write d_out ---
    wround_kernel<<<(640 * 64 + 255) / 256, 256>>>(root3, W3, 64);
    aggx_kernel<<<agg_blocks, 256>>>(bufA, N);
    gemm_tc_kernel<<<dim3(1, nby), 256>>>(bufA, agg, b3, (float*)d_out, 64, N, 64, 0);
}